// round 10
// baseline (speedup 1.0000x reference)
#include <cuda_runtime.h>
#include <stdint.h>

#define N_PTS   50000
#define B_ROWS  512
#define E_DIM   16
#define KSEL    20
#define BTHR    256
#define G_ROWS  8
#define SPLITS  2
#define NGRP    (B_ROWS / G_ROWS)      // 64
#define NBLK    (NGRP * 2 * SPLITS)    // 256
#define HID     64
#define FULLM   0xffffffffu

typedef unsigned long long ull;
typedef unsigned int uint;

__device__ float g_feats[B_ROWS][8];
__device__ float g_pval[2][NGRP][SPLITS][G_ROWS][KSEL];
__device__ int   g_pidx[2][NGRP][SPLITS][G_ROWS][KSEL];
__device__ int   g_flag[2][NGRP];
__device__ int   g_done = 0;

static __device__ __forceinline__ float finf() { return __int_as_float(0x7f800000); }

// order-preserving float -> uint key (for atomicMin thresholds)
static __device__ __forceinline__ uint fkey(float f) {
    uint u = __float_as_uint(f);
    return (u & 0x80000000u) ? ~u : (u | 0x80000000u);
}
static __device__ __forceinline__ float funkey(uint k) {
    uint u = (k & 0x80000000u) ? (k & 0x7fffffffu) : ~k;
    return __uint_as_float(u);
}

static __device__ __forceinline__ ull pk2(float lo, float hi) {
    ull r; asm("mov.b64 %0,{%1,%2};" : "=l"(r) : "f"(lo), "f"(hi)); return r;
}
static __device__ __forceinline__ void upk2(ull v, float& lo, float& hi) {
    asm("mov.b64 {%0,%1},%2;" : "=f"(lo), "=f"(hi) : "l"(v));
}
static __device__ __forceinline__ ull fma2(ull a, ull b, ull c) {
    ull d; asm("fma.rn.f32x2 %0,%1,%2,%3;" : "=l"(d) : "l"(a), "l"(b), "l"(c)); return d;
}

// ---------------------------------------------------------------------------
// Barrier-free warp-autonomous KNN.
// grid = (64 groups, 2 sets, 2 splits) x 256 threads (8 warps), occ 2/SM.
// Within a warp: lanes 4c..4c+3 co-own candidate c; lane owns dims 4*(lane&3).
// q2 = 8 rows x 2 ull in regs. Partial s combined via shfl reduce-scatter:
// lane g4 ends with full s for rows {g4, g4+4}. Hits -> 2 ballots ->
// warp-distributed sorted top-20 lists (8 per warp), gated by a block-shared
// monotone threshold (atomicMin smem). NO __syncthreads in the main loop.
// ---------------------------------------------------------------------------
__global__ __launch_bounds__(BTHR, 2)
void knn_kernel(const float* __restrict__ emb0, const float* __restrict__ emb1,
                const float* __restrict__ rctx0, const float* __restrict__ rctx1,
                const int* __restrict__ idx0, const int* __restrict__ idx1,
                const float* __restrict__ mean_in, const float* __restrict__ std_in,
                const float* __restrict__ W1, const float* __restrict__ b1,
                const float* __restrict__ Wm, const float* __restrict__ bm,
                const float* __restrict__ Ws, const float* __restrict__ bs,
                float* __restrict__ out, int n) {
    const int grp   = blockIdx.x;
    const int set   = blockIdx.y;
    const int split = blockIdx.z;
    const float* __restrict__ emb  = set ? emb1 : emb0;
    const float* __restrict__ rctx = set ? rctx1 : rctx0;
    const int*   __restrict__ idxp = set ? idx1 : idx0;

    const int rowbase = grp * G_ROWS;
    const int tid  = threadIdx.x;
    const int lane = tid & 31;
    const int w    = tid >> 5;          // warp id
    const int g4   = lane & 3;          // dim-quad slot; owns rows {g4, g4+4}
    const int cid  = lane >> 2;         // candidate slot within warp (0..7)

    __shared__ uint th_sm[G_ROWS];                 // block-shared gate keys
    __shared__ ull  lst[G_ROWS][G_ROWS][KSEL];     // [warp][row][k] packed
    __shared__ int  smflag[2];

    if (tid < G_ROWS) th_sm[tid] = fkey(finf());

    // ---- queries: 8 rows x own 4 dims, packed -2*q ----
    ull q2[G_ROWS][2];
#pragma unroll
    for (int r = 0; r < G_ROWS; r++) {
        int si = idxp[rowbase + r];
        float4 v = *reinterpret_cast<const float4*>(emb + (size_t)si * E_DIM + 4 * g4);
        q2[r][0] = pk2(-2.f * v.x, -2.f * v.y);
        q2[r][1] = pk2(-2.f * v.z, -2.f * v.w);
    }
    const int self_lo = idxp[rowbase + g4];
    const int self_hi = idxp[rowbase + 4 + g4];
    __syncthreads();                    // th_sm init visible

    const int halfn = (n + SPLITS - 1) / SPLITS;
    const int jbeg  = split * halfn;
    const int jend  = min(n, jbeg + halfn);
    const int nit   = (jend - jbeg + 63) >> 6;      // 64 cands per block-iter

    // ---- 8 warp-distributed top-20 lists ----
    float kv[8], th[8];
    int   ki[8];
#pragma unroll
    for (int r = 0; r < 8; r++) { kv[r] = finf(); th[r] = finf(); ki[r] = -1; }

    const int grp2 = (g4 >> 1) & 1;
    const int par  = g4 & 1;

    // prefetch iter 0
    ull e0c, e1c, e0n, e1n;
    {
        int jc = min(jbeg + 8 * w + cid, jend - 1);
        ulonglong2 pp = *reinterpret_cast<const ulonglong2*>(
            emb + (size_t)jc * E_DIM + 4 * g4);
        e0c = pp.x; e1c = pp.y;
    }

    for (int it = 0; it < nit; it++) {
        const int jb = jbeg + (it << 6) + 8 * w;
        {   // prefetch next chunk (clamped address, filtered later)
            int jc = min(jb + 64 + cid, jend - 1);
            ulonglong2 pp = *reinterpret_cast<const ulonglong2*>(
                emb + (size_t)jc * E_DIM + 4 * g4);
            e0n = pp.x; e1n = pp.y;
        }
        // partial s over own 4 dims: |e|^2 - 2 a.e (per-dim form)
        ull nrm = fma2(e1c, e1c, fma2(e0c, e0c, 0ULL));
        float p[8];
#pragma unroll
        for (int r = 0; r < 8; r++) {
            ull a = fma2(q2[r][1], e1c, fma2(q2[r][0], e0c, nrm));
            float lo, hi; upk2(a, lo, hi);
            p[r] = lo + hi;
        }
        // reduce-scatter over the 4-lane quad
        float s0 = grp2 ? p[0] : p[2];
        float s1 = grp2 ? p[1] : p[3];
        float s2 = grp2 ? p[4] : p[6];
        float s3 = grp2 ? p[5] : p[7];
        float r0 = __shfl_xor_sync(FULLM, s0, 2);
        float r1 = __shfl_xor_sync(FULLM, s1, 2);
        float r2 = __shfl_xor_sync(FULLM, s2, 2);
        float r3 = __shfl_xor_sync(FULLM, s3, 2);
        float a0 = (grp2 ? p[2] : p[0]) + r0;
        float a1 = (grp2 ? p[3] : p[1]) + r1;
        float a2 = (grp2 ? p[6] : p[4]) + r2;
        float a3 = (grp2 ? p[7] : p[5]) + r3;
        float t0 = par ? a0 : a1;
        float t1 = par ? a2 : a3;
        float u0 = __shfl_xor_sync(FULLM, t0, 1);
        float u1 = __shfl_xor_sync(FULLM, t1, 1);
        float s_lo = (par ? a1 : a0) + u0;   // full s, row g4
        float s_hi = (par ? a3 : a2) + u1;   // full s, row g4+4

        // block-shared monotone gate (stale-safe)
        float tg_lo = funkey(*(volatile uint*)&th_sm[g4]);
        float tg_hi = funkey(*(volatile uint*)&th_sm[4 + g4]);
        int j = jb + cid;
        bool oklo = (s_lo < tg_lo) && (j != self_lo) && (j < jend);
        bool okhi = (s_hi < tg_hi) && (j != self_hi) && (j < jend);
        uint blo = __ballot_sync(FULLM, oklo);
        uint bhi = __ballot_sync(FULLM, okhi);

        if (blo | bhi) {                       // rare after warm-up
#pragma unroll
            for (int r = 0; r < 4; r++) {
                uint mlo = blo & (0x11111111u << r);
                uint m = mlo;
                while (m) {
                    int src = __ffs(m) - 1; m &= m - 1;
                    float bv = __shfl_sync(FULLM, s_lo, src);
                    int   bj = jb + (src >> 2);
                    if (bv < th[r]) {
                        float pv = __shfl_up_sync(FULLM, kv[r], 1);
                        int   pj = __shfl_up_sync(FULLM, ki[r], 1);
                        if (lane < KSEL && bv < kv[r]) {
                            if (lane == 0 || bv >= pv) { kv[r] = bv; ki[r] = bj; }
                            else                        { kv[r] = pv; ki[r] = pj; }
                        }
                        th[r] = __shfl_sync(FULLM, kv[r], KSEL - 1);
                    }
                }
                if (mlo && lane == 0) atomicMin(&th_sm[r], fkey(th[r]));

                uint mhi = bhi & (0x11111111u << r);
                m = mhi;
                while (m) {
                    int src = __ffs(m) - 1; m &= m - 1;
                    float bv = __shfl_sync(FULLM, s_hi, src);
                    int   bj = jb + (src >> 2);
                    if (bv < th[4 + r]) {
                        float pv = __shfl_up_sync(FULLM, kv[4 + r], 1);
                        int   pj = __shfl_up_sync(FULLM, ki[4 + r], 1);
                        if (lane < KSEL && bv < kv[4 + r]) {
                            if (lane == 0 || bv >= pv) { kv[4 + r] = bv; ki[4 + r] = bj; }
                            else                        { kv[4 + r] = pv; ki[4 + r] = pj; }
                        }
                        th[4 + r] = __shfl_sync(FULLM, kv[4 + r], KSEL - 1);
                    }
                }
                if (mhi && lane == 0) atomicMin(&th_sm[4 + r], fkey(th[4 + r]));
            }
        }
        e0c = e0n; e1c = e1n;
    }

    // ---- intra-block merge: warp w builds final list for row w ----
    if (lane < KSEL) {
#pragma unroll
        for (int r = 0; r < G_ROWS; r++)
            lst[w][r][lane] = (((ull)(uint)ki[r]) << 32) | __float_as_uint(kv[r]);
    }
    __syncthreads();

    float kvF = finf(), thF = finf();
    int   kiF = -1;
#pragma unroll 1
    for (int w2 = 0; w2 < G_ROWS; w2++) {
        float bvl = finf(); int bjl = -1;
        if (lane < KSEL) {
            ull ent = lst[w2][w][lane];
            bvl = __uint_as_float((uint)ent);
            bjl = (int)(ent >> 32);
        }
        uint m = __ballot_sync(FULLM, bvl < thF);
        while (m) {
            int src = __ffs(m) - 1; m &= m - 1;
            float bv = __shfl_sync(FULLM, bvl, src);
            int   bj = __shfl_sync(FULLM, bjl, src);
            if (bv < thF) {
                float pv = __shfl_up_sync(FULLM, kvF, 1);
                int   pj = __shfl_up_sync(FULLM, kiF, 1);
                if (lane < KSEL && bv < kvF) {
                    if (lane == 0 || bv >= pv) { kvF = bv; kiF = bj; }
                    else                        { kvF = pv; kiF = pj; }
                }
                thF = __shfl_sync(FULLM, kvF, KSEL - 1);
            }
        }
    }

    // ---- split rendezvous ----
    if (lane < KSEL) {
        g_pval[set][grp][split][w][lane] = kvF;
        g_pidx[set][grp][split][w][lane] = kiF;
    }
    __threadfence();
    __syncthreads();
    if (tid == 0) smflag[0] = atomicAdd(&g_flag[set][grp], 1);
    __syncthreads();

    if (smflag[0] == 1) {               // second arrival merges + features
        __threadfence();
        const int po = 1 - split;
#pragma unroll 1
        for (int i = 0; i < KSEL; i++) {
            float bv = g_pval[set][grp][po][w][i];
            int   bj = g_pidx[set][grp][po][w][i];
            if (bv < thF) {
                float pv = __shfl_up_sync(FULLM, kvF, 1);
                int   pj = __shfl_up_sync(FULLM, kiF, 1);
                if (lane < KSEL && bv < kvF) {
                    if (lane == 0 || bv >= pv) { kvF = bv; kiF = bj; }
                    else                        { kvF = pv; kiF = pj; }
                }
                thF = __shfl_sync(FULLM, kvF, KSEL - 1);
            }
        }
        // |a|^2 for row w (reload query row, warp reduce)
        int si = idxp[rowbase + w];
        float pa = 0.f;
        if (lane < E_DIM) {
            float vv = emb[(size_t)si * E_DIM + lane];
            pa = vv * vv;
        }
#pragma unroll
        for (int off = 16; off; off >>= 1) pa += __shfl_xor_sync(FULLM, pa, off);
        const float na = pa;

        const int row = rowbase + w;
        float wgt = 0.f, sel = 0.f;
        if (lane < KSEL) {
            float d2  = fmaxf(kvF + na, 0.f);
            float sim = sqrtf(d2) + 0.001f;
            wgt = __expf(-sim);
            sel = rctx[(size_t)row * n + kiF];
        }
        float sw = wgt, ssw = sel * wgt, ss = sel, ss2 = sel * sel;
#pragma unroll
        for (int off = 16; off; off >>= 1) {
            sw  += __shfl_xor_sync(FULLM, sw,  off);
            ssw += __shfl_xor_sync(FULLM, ssw, off);
            ss  += __shfl_xor_sync(FULLM, ss,  off);
            ss2 += __shfl_xor_sync(FULLM, ss2, off);
        }
        if (lane == 0) {
            g_feats[row][0 + set] = sw;
            g_feats[row][2 + set] = ssw / sw;
            float var = (ss2 - ss * ss / (float)KSEL) / (float)(KSEL - 1);
            g_feats[row][4 + set] = sqrtf(fmaxf(var, 0.f));
        }
        if (tid == 0) g_flag[set][grp] = 0;
    }

    // ---- global tail: MLP ----
    __threadfence();
    __syncthreads();
    if (tid == 0) smflag[1] = atomicAdd(&g_done, 1);
    __syncthreads();
    if (smflag[1] != NBLK - 1) return;
    __threadfence();

#pragma unroll
    for (int rr = 0; rr < 2; rr++) {
        int r = tid + BTHR * rr;
        float f[8];
#pragma unroll
        for (int i = 0; i < 6; i++) f[i] = g_feats[r][i];
        f[6] = mean_in[r];
        f[7] = std_in[r];
        float m = bm[0], sd = bs[0];
#pragma unroll 4
        for (int jj = 0; jj < HID; jj++) {
            float h = b1[jj];
#pragma unroll
            for (int i = 0; i < 8; i++) h = fmaf(f[i], W1[i * HID + jj], h);
            h = fmaxf(h, 0.f);
            m  = fmaf(h, Wm[jj], m);
            sd = fmaf(h, Ws[jj], sd);
        }
        out[r]          = m;
        out[B_ROWS + r] = sd;
    }
    if (tid == 0) g_done = 0;
}

// ---------------------------------------------------------------------------
extern "C" void kernel_launch(void* const* d_in, const int* in_sizes, int n_in,
                              void* d_out, int out_size) {
    const float* emb0    = (const float*)d_in[0];
    const float* emb1    = (const float*)d_in[1];
    const float* rctx0   = (const float*)d_in[2];
    const float* rctx1   = (const float*)d_in[3];
    const int*   idx0    = (const int*)  d_in[4];
    const int*   idx1    = (const int*)  d_in[5];
    const float* mean_in = (const float*)d_in[6];
    const float* std_in  = (const float*)d_in[7];
    const float* W1      = (const float*)d_in[8];
    const float* b1      = (const float*)d_in[9];
    const float* Wm      = (const float*)d_in[10];
    const float* bm      = (const float*)d_in[11];
    const float* Ws      = (const float*)d_in[12];
    const float* bs      = (const float*)d_in[13];

    int n = in_sizes[0] / E_DIM;    // 50000

    dim3 grid(NGRP, 2, SPLITS);
    knn_kernel<<<grid, BTHR>>>(emb0, emb1, rctx0, rctx1, idx0, idx1,
                               mean_in, std_in, W1, b1, Wm, bm, Ws, bs,
                               (float*)d_out, n);
}

// round 11
// speedup vs baseline: 1.3235x; 1.3235x over previous
#include <cuda_runtime.h>
#include <stdint.h>

#define N_PTS   50000
#define B_ROWS  512
#define E_DIM   16
#define KSEL    20
#define KP1     21           // top-21; lane 0 is always "self", dropped at the end
#define TILE    512          // candidates per main tile (2 per thread)
#define WARM    512          // warm-up candidates (per row, direct scatter)
#define BTHR    256
#define G_ROWS  8
#define SPLITS  6
#define NGRP    (B_ROWS / G_ROWS)        // 64
#define NBLK    (NGRP * 2 * SPLITS)      // 768
#define HID     64
#define FULLM   0xffffffffu

typedef unsigned long long ull;
typedef unsigned int uint;

__device__ float g_feats[B_ROWS][8];
__device__ float g_pval[2][NGRP][SPLITS][G_ROWS][KP1];
__device__ int   g_pidx[2][NGRP][SPLITS][G_ROWS][KP1];
__device__ int   g_flag[2][NGRP];
__device__ int   g_done = 0;

static __device__ __forceinline__ float finf() { return __int_as_float(0x7f800000); }

static __device__ __forceinline__ ull pk2(float lo, float hi) {
    ull r; asm("mov.b64 %0,{%1,%2};" : "=l"(r) : "f"(lo), "f"(hi)); return r;
}
static __device__ __forceinline__ void upk2(ull v, float& lo, float& hi) {
    asm("mov.b64 {%0,%1},%2;" : "=f"(lo), "=f"(hi) : "l"(v));
}
static __device__ __forceinline__ ull fma2(ull a, ull b, ull c) {
    ull d; asm("fma.rn.f32x2 %0,%1,%2,%3;" : "=l"(d) : "l"(a), "l"(b), "l"(c)); return d;
}
static __device__ __forceinline__ ull add2(ull a, ull b) {
    ull d; asm("add.rn.f32x2 %0,%1,%2;" : "=l"(d) : "l"(a), "l"(b)); return d;
}

// ---------------------------------------------------------------------------
// In-register-gated KNN with per-row smem queues.
// grid = (64 groups, 2 sets, 6 splits) = 768 blocks x 256 threads, occ 3.
// Phase A: thread computes s = |e|^2 - 2 a_r.e for 2 cands x 8 rows
//          (q broadcast from smem); gates IN REGISTERS vs cached per-row
//          thresholds; pushes rare hits into per-row queues (atomicAdd).
// Drain:   warp w empties row w's queue into its warp-distributed top-21.
// Warm-up: warp w scans the first 512 cands of its split for row w directly,
//          seeding tight thresholds (no flood).
// ---------------------------------------------------------------------------
__global__ __launch_bounds__(BTHR, 3)
void knn_kernel(const float* __restrict__ emb0, const float* __restrict__ emb1,
                const float* __restrict__ rctx0, const float* __restrict__ rctx1,
                const int* __restrict__ idx0, const int* __restrict__ idx1,
                const float* __restrict__ mean_in, const float* __restrict__ std_in,
                const float* __restrict__ W1, const float* __restrict__ b1,
                const float* __restrict__ Wm, const float* __restrict__ bm,
                const float* __restrict__ Ws, const float* __restrict__ bs,
                float* __restrict__ out, int n) {
    const int grp   = blockIdx.x;
    const int set   = blockIdx.y;
    const int split = blockIdx.z;
    const float* __restrict__ emb  = set ? emb1 : emb0;
    const float* __restrict__ rctx = set ? rctx1 : rctx0;
    const int*   __restrict__ idxp = set ? idx1 : idx0;

    const int rowbase = grp * G_ROWS;
    const int tid  = threadIdx.x;
    const int lane = tid & 31;
    const int w    = tid >> 5;          // warp id == owned row

    __shared__ __align__(16) ull   q_sm[G_ROWS][8];   // [row][kull], packed -2q
    __shared__ float na_sm[G_ROWS];
    __shared__ __align__(16) float th_sm[G_ROWS];
    __shared__ float qv[G_ROWS][TILE];
    __shared__ int   qi[G_ROWS][TILE];
    __shared__ int   qcnt[G_ROWS];
    __shared__ int   smflag[2];

    // ---- stage queries: warp r handles row r ----
    {
        int si = 0;
        if (lane == 0) si = idxp[rowbase + w];
        si = __shfl_sync(FULLM, si, 0);
        float nx = 0.f;
        if (lane < 8) {
            float2 v = reinterpret_cast<const float2*>(emb + (size_t)si * E_DIM)[lane];
            nx = v.x * v.x + v.y * v.y;
            q_sm[w][lane] = pk2(-2.f * v.x, -2.f * v.y);
        }
        nx += __shfl_xor_sync(FULLM, nx, 4);
        nx += __shfl_xor_sync(FULLM, nx, 2);
        nx += __shfl_xor_sync(FULLM, nx, 1);
        if (lane == 0) na_sm[w] = nx;
    }
    if (tid < G_ROWS) qcnt[tid] = 0;
    __syncthreads();

    const int halfn = (n + SPLITS - 1) / SPLITS;
    const int jbeg  = split * halfn;
    const int jend  = min(n, jbeg + halfn);

    // ---- top-21 state (lanes 0..20 ascending) ----
    float kval   = finf();
    int   kidx   = -1;
    float thresh = finf();

    auto insert = [&](float bv, int bj) {
        float pv = __shfl_up_sync(FULLM, kval, 1);
        int   pj = __shfl_up_sync(FULLM, kidx, 1);
        if (lane < KP1 && bv < kval) {
            if (lane == 0 || bv >= pv) { kval = bv; kidx = bj; }
            else                        { kval = pv; kidx = pj; }
        }
        thresh = __shfl_sync(FULLM, kval, KP1 - 1);
    };
    auto scatter = [&](float bvl, int bjl, bool act) {
        uint m = __ballot_sync(FULLM, act && bvl < thresh);
        while (m) {
            int src = __ffs(m) - 1; m &= m - 1;
            float bv = __shfl_sync(FULLM, bvl, src);
            int   bj = __shfl_sync(FULLM, bjl, src);
            if (bv < thresh) insert(bv, bj);
        }
    };

    // ================= warm-up: warp w scans first WARM cands for row w =====
    {
        const ulonglong2* qp = reinterpret_cast<const ulonglong2*>(&q_sm[w][0]);
        ulonglong2 qa = qp[0], qb = qp[1], qc = qp[2], qd = qp[3];
#pragma unroll 1
        for (int c = 0; c < WARM / 32; c++) {
            int j = jbeg + 32 * c + lane;       // jend-jbeg >= WARM always
            const ulonglong2* p = reinterpret_cast<const ulonglong2*>(
                emb + (size_t)j * E_DIM);
            ulonglong2 x = p[0], y = p[1], z = p[2], u = p[3];
            ull nA = fma2(x.x, x.x, 0ULL), nB = fma2(x.y, x.y, 0ULL);
            nA = fma2(y.x, y.x, nA);  nB = fma2(y.y, y.y, nB);
            nA = fma2(z.x, z.x, nA);  nB = fma2(z.y, z.y, nB);
            nA = fma2(u.x, u.x, nA);  nB = fma2(u.y, u.y, nB);
            ull a = add2(nA, nB);
            a = fma2(qa.x, x.x, a);  a = fma2(qa.y, x.y, a);
            a = fma2(qb.x, y.x, a);  a = fma2(qb.y, y.y, a);
            a = fma2(qc.x, z.x, a);  a = fma2(qc.y, z.y, a);
            a = fma2(qd.x, u.x, a);  a = fma2(qd.y, u.y, a);
            float lo, hi; upk2(a, lo, hi);
            scatter(lo + hi, j, true);
        }
        if (lane == 0) th_sm[w] = thresh;
    }
    __syncthreads();

    // ================= main loop =================
    const int base   = jbeg + WARM;
    const int ntiles = (jend - base + TILE - 1) / TILE;

    for (int t = 0; t < ntiles; t++) {
        // thresholds (updated by previous drain, barrier-ordered)
        float4 tA = *reinterpret_cast<const float4*>(&th_sm[0]);
        float4 tB = *reinterpret_cast<const float4*>(&th_sm[4]);
        const float thr[8] = {tA.x, tA.y, tA.z, tA.w, tB.x, tB.y, tB.z, tB.w};

        const int j0 = base + t * TILE + tid;
        const int j1 = j0 + BTHR;
        const bool v0 = (j0 < jend), v1 = (j1 < jend);
        const int c0 = min(j0, jend - 1), c1 = min(j1, jend - 1);

        ull e0[8], e1[8];
        {
            const ulonglong2* p = reinterpret_cast<const ulonglong2*>(emb + (size_t)c0 * E_DIM);
            ulonglong2 a = p[0], b = p[1], c = p[2], d = p[3];
            e0[0]=a.x; e0[1]=a.y; e0[2]=b.x; e0[3]=b.y; e0[4]=c.x; e0[5]=c.y; e0[6]=d.x; e0[7]=d.y;
        }
        {
            const ulonglong2* p = reinterpret_cast<const ulonglong2*>(emb + (size_t)c1 * E_DIM);
            ulonglong2 a = p[0], b = p[1], c = p[2], d = p[3];
            e1[0]=a.x; e1[1]=a.y; e1[2]=b.x; e1[3]=b.y; e1[4]=c.x; e1[5]=c.y; e1[6]=d.x; e1[7]=d.y;
        }
        // packed candidate norms
        ull n0A = fma2(e0[0], e0[0], 0ULL), n0B = fma2(e0[1], e0[1], 0ULL);
        ull n1A = fma2(e1[0], e1[0], 0ULL), n1B = fma2(e1[1], e1[1], 0ULL);
#pragma unroll
        for (int k = 2; k < 8; k += 2) {
            n0A = fma2(e0[k], e0[k], n0A);   n0B = fma2(e0[k+1], e0[k+1], n0B);
            n1A = fma2(e1[k], e1[k], n1A);   n1B = fma2(e1[k+1], e1[k+1], n1B);
        }
        const ull nrm0 = add2(n0A, n0B), nrm1 = add2(n1A, n1B);

#pragma unroll
        for (int r = 0; r < G_ROWS; r++) {
            const ulonglong2* qp = reinterpret_cast<const ulonglong2*>(&q_sm[r][0]);
            ulonglong2 qa = qp[0], qb = qp[1], qc = qp[2], qd = qp[3];
            ull a0 = nrm0, a1 = nrm1;
            a0 = fma2(qa.x, e0[0], a0);  a1 = fma2(qa.x, e1[0], a1);
            a0 = fma2(qa.y, e0[1], a0);  a1 = fma2(qa.y, e1[1], a1);
            a0 = fma2(qb.x, e0[2], a0);  a1 = fma2(qb.x, e1[2], a1);
            a0 = fma2(qb.y, e0[3], a0);  a1 = fma2(qb.y, e1[3], a1);
            a0 = fma2(qc.x, e0[4], a0);  a1 = fma2(qc.x, e1[4], a1);
            a0 = fma2(qc.y, e0[5], a0);  a1 = fma2(qc.y, e1[5], a1);
            a0 = fma2(qd.x, e0[6], a0);  a1 = fma2(qd.x, e1[6], a1);
            a0 = fma2(qd.y, e0[7], a0);  a1 = fma2(qd.y, e1[7], a1);
            float l0, h0, l1, h1;
            upk2(a0, l0, h0);
            upk2(a1, l1, h1);
            float s0 = l0 + h0, s1 = l1 + h1;
            if (v0 && s0 < thr[r]) {
                int p = atomicAdd(&qcnt[r], 1);
                qv[r][p] = s0; qi[r][p] = j0;
            }
            if (v1 && s1 < thr[r]) {
                int p = atomicAdd(&qcnt[r], 1);
                qv[r][p] = s1; qi[r][p] = j1;
            }
        }
        __syncthreads();

        // ---- drain: warp w empties row w's queue ----
        int m = qcnt[w];
        for (int b0 = 0; b0 < m; b0 += 32) {
            bool  act = (b0 + lane < m);
            float bvl = act ? qv[w][b0 + lane] : finf();
            int   bjl = act ? qi[w][b0 + lane] : 0;
            scatter(bvl, bjl, act);
        }
        if (lane == 0) { qcnt[w] = 0; th_sm[w] = thresh; }
        __syncthreads();
    }

    // ================= split rendezvous (6 partials) =================
    if (lane < KP1) {
        g_pval[set][grp][split][w][lane] = kval;
        g_pidx[set][grp][split][w][lane] = kidx;
    }
    __threadfence();
    __syncthreads();
    if (tid == 0) smflag[0] = atomicAdd(&g_flag[set][grp], 1);
    __syncthreads();

    if (smflag[0] == SPLITS - 1) {          // last arrival merges + features
        __threadfence();
#pragma unroll 1
        for (int s2 = 0; s2 < SPLITS; s2++) {
            if (s2 == split) continue;
            for (int i = 0; i < KP1; i++) {
                float bv = g_pval[set][grp][s2][w][i];
                int   bj = g_pidx[set][grp][s2][w][i];
                if (bv < thresh) insert(bv, bj);
            }
        }
        // lane 0 = "self" (s = -|a|^2, strict global min): dropped
        const int row = rowbase + w;
        const float na = na_sm[w];
        float wgt = 0.f, sel = 0.f;
        if (lane >= 1 && lane < KP1) {
            float d2  = fmaxf(kval + na, 0.f);
            float sim = sqrtf(d2) + 0.001f;
            wgt = __expf(-sim);
            sel = rctx[(size_t)row * n + kidx];
        }
        float sw = wgt, ssw = sel * wgt, ss = sel, ss2 = sel * sel;
#pragma unroll
        for (int off = 16; off; off >>= 1) {
            sw  += __shfl_xor_sync(FULLM, sw,  off);
            ssw += __shfl_xor_sync(FULLM, ssw, off);
            ss  += __shfl_xor_sync(FULLM, ss,  off);
            ss2 += __shfl_xor_sync(FULLM, ss2, off);
        }
        if (lane == 0) {
            g_feats[row][0 + set] = sw;
            g_feats[row][2 + set] = ssw / sw;
            float var = (ss2 - ss * ss / (float)KSEL) / (float)(KSEL - 1);
            g_feats[row][4 + set] = sqrtf(fmaxf(var, 0.f));
        }
        if (tid == 0) g_flag[set][grp] = 0;
    }

    // ================= global tail: MLP =================
    __threadfence();
    __syncthreads();
    if (tid == 0) smflag[1] = atomicAdd(&g_done, 1);
    __syncthreads();
    if (smflag[1] != NBLK - 1) return;
    __threadfence();

#pragma unroll
    for (int rr = 0; rr < 2; rr++) {
        int r = tid + BTHR * rr;
        float f[8];
#pragma unroll
        for (int i = 0; i < 6; i++) f[i] = g_feats[r][i];
        f[6] = mean_in[r];
        f[7] = std_in[r];
        float m = bm[0], sd = bs[0];
#pragma unroll 4
        for (int jj = 0; jj < HID; jj++) {
            float h = b1[jj];
#pragma unroll
            for (int i = 0; i < 8; i++) h = fmaf(f[i], W1[i * HID + jj], h);
            h = fmaxf(h, 0.f);
            m  = fmaf(h, Wm[jj], m);
            sd = fmaf(h, Ws[jj], sd);
        }
        out[r]          = m;
        out[B_ROWS + r] = sd;
    }
    if (tid == 0) g_done = 0;
}

// ---------------------------------------------------------------------------
extern "C" void kernel_launch(void* const* d_in, const int* in_sizes, int n_in,
                              void* d_out, int out_size) {
    const float* emb0    = (const float*)d_in[0];
    const float* emb1    = (const float*)d_in[1];
    const float* rctx0   = (const float*)d_in[2];
    const float* rctx1   = (const float*)d_in[3];
    const int*   idx0    = (const int*)  d_in[4];
    const int*   idx1    = (const int*)  d_in[5];
    const float* mean_in = (const float*)d_in[6];
    const float* std_in  = (const float*)d_in[7];
    const float* W1      = (const float*)d_in[8];
    const float* b1      = (const float*)d_in[9];
    const float* Wm      = (const float*)d_in[10];
    const float* bm      = (const float*)d_in[11];
    const float* Ws      = (const float*)d_in[12];
    const float* bs      = (const float*)d_in[13];

    int n = in_sizes[0] / E_DIM;    // 50000

    dim3 grid(NGRP, 2, SPLITS);
    knn_kernel<<<grid, BTHR>>>(emb0, emb1, rctx0, rctx1, idx0, idx1,
                               mean_in, std_in, W1, b1, Wm, bm, Ws, bs,
                               (float*)d_out, n);
}